// round 12
// baseline (speedup 1.0000x reference)
#include <cuda_runtime.h>
#include <cuda_bf16.h>
#include <cstdint>

#define NROWS 100000
#define INDIM 256
#define HID   64
#define OUTD  64

// scratch (device globals: no allocation allowed)
__device__ __align__(16) float g_H[(size_t)NROWS * HID];
__device__ __align__(16) float g_O[(size_t)NROWS * OUTD];

// m16n8k16 bf16 MMA, f32 accumulate (baseline PTX, works on .target sm_103)
#define MMA_BF16(c0, c1, c2, c3, a0, a1, a2, a3, b0, b1)                      \
    asm volatile(                                                             \
        "mma.sync.aligned.m16n8k16.row.col.f32.bf16.bf16.f32 "                \
        "{%0,%1,%2,%3}, {%4,%5,%6,%7}, {%8,%9}, {%0,%1,%2,%3};"               \
        : "+f"(c0), "+f"(c1), "+f"(c2), "+f"(c3)                              \
        : "r"(a0), "r"(a1), "r"(a2), "r"(a3), "r"(b0), "r"(b1))

// L2 evict_last policy (created once per thread; cheap U-pipe op)
__device__ __forceinline__ uint64_t mk_evict_last_policy() {
    uint64_t pol;
    asm("createpolicy.fractional.L2::evict_last.b64 %0, 1.0;" : "=l"(pol));
    return pol;
}
// resident store: pin H / O lines in L2 for the following gather kernel
__device__ __forceinline__ void stg_f2_resident(float* p, float2 v, uint64_t pol) {
    asm volatile("st.global.L2::cache_hint.v2.f32 [%0], {%1,%2}, %3;"
                 :: "l"(p), "f"(v.x), "f"(v.y), "l"(pol) : "memory");
}

// split a float2 into packed bf16x2 hi + bf16x2 lo (residual)
__device__ __forceinline__ void cvt_split(float2 v, uint32_t& hi, uint32_t& lo) {
    uint32_t h;
    asm("cvt.rn.bf16x2.f32 %0, %1, %2;" : "=r"(h) : "f"(v.y), "f"(v.x));
    const float h0 = __uint_as_float(h << 16);
    const float h1 = __uint_as_float(h & 0xffff0000u);
    const float r0 = v.x - h0;
    const float r1 = v.y - h1;
    uint32_t l;
    asm("cvt.rn.bf16x2.f32 %0, %1, %2;" : "=r"(l) : "f"(r1), "f"(r0));
    hi = h;
    lo = l;
}

#define BSTRIDE 264   // 256 + 8 bf16 padding -> conflict-free B-fragment LDS

// ---------------------------------------------------------------------------
// Kernel 1: H = X @ W1 via warp-level bf16 MMA, split-2 (3 MMAs), f32 accum.
// X loads: streaming (__ldcs). H stores: L2 evict_last via cache_hint.
// ---------------------------------------------------------------------------
__global__ void __launch_bounds__(256, 2) gemm1_mma_kernel(
    const float* __restrict__ X, const float* __restrict__ W1,
    float* __restrict__ H)
{
    extern __shared__ __nv_bfloat16 wsm[];
    __nv_bfloat16* Bhi = wsm;                 // [64][BSTRIDE]
    __nv_bfloat16* Blo = wsm + 64 * BSTRIDE;  // [64][BSTRIDE]

    const int tid = threadIdx.x;

    for (int idx = tid; idx < INDIM * HID; idx += 256) {
        const int k = idx >> 6;
        const int n = idx & 63;
        const float w = W1[idx];
        const __nv_bfloat16 hb = __float2bfloat16(w);
        const float hf = __bfloat162float(hb);
        Bhi[n * BSTRIDE + k] = hb;
        Blo[n * BSTRIDE + k] = __float2bfloat16(w - hf);
    }
    __syncthreads();

    const int warp  = tid >> 5;
    const int lane  = tid & 31;
    const int rbase = blockIdx.x * 256 + warp * 32;
    if (rbase >= NROWS) return;

    const int rq = lane >> 2;
    const int cq = (lane & 3) * 2;

    const int r00 = rbase + rq;
    const int r01 = r00 + 8;
    const int r10 = rbase + 16 + rq;
    const int r11 = r10 + 8;
    const float2* px[2][2];
    px[0][0] = reinterpret_cast<const float2*>(X + (size_t)min(r00, NROWS - 1) * INDIM);
    px[0][1] = reinterpret_cast<const float2*>(X + (size_t)min(r01, NROWS - 1) * INDIM);
    px[1][0] = reinterpret_cast<const float2*>(X + (size_t)min(r10, NROWS - 1) * INDIM);
    px[1][1] = reinterpret_cast<const float2*>(X + (size_t)min(r11, NROWS - 1) * INDIM);

    float acc[2][8][4];
    #pragma unroll
    for (int m = 0; m < 2; ++m)
        #pragma unroll
        for (int n = 0; n < 8; ++n)
            #pragma unroll
            for (int i = 0; i < 4; ++i) acc[m][n][i] = 0.f;

    float2 fb[2][2][4];
    const int h = cq >> 1;   // float2 index of cq

    #pragma unroll
    for (int m = 0; m < 2; ++m) {
        fb[0][m][0] = __ldcs(px[m][0] + h);
        fb[0][m][1] = __ldcs(px[m][1] + h);
        fb[0][m][2] = __ldcs(px[m][0] + h + 4);
        fb[0][m][3] = __ldcs(px[m][1] + h + 4);
    }

    #pragma unroll
    for (int ks = 0; ks < 16; ++ks) {
        const int cur = ks & 1;
        if (ks < 15) {
            const int kb8 = (ks + 1) * 8;   // float2 units
            #pragma unroll
            for (int m = 0; m < 2; ++m) {
                fb[cur ^ 1][m][0] = __ldcs(px[m][0] + kb8 + h);
                fb[cur ^ 1][m][1] = __ldcs(px[m][1] + kb8 + h);
                fb[cur ^ 1][m][2] = __ldcs(px[m][0] + kb8 + h + 4);
                fb[cur ^ 1][m][3] = __ldcs(px[m][1] + kb8 + h + 4);
            }
        }

        uint32_t ahi[2][4], alo[2][4];
        #pragma unroll
        for (int m = 0; m < 2; ++m) {
            cvt_split(fb[cur][m][0], ahi[m][0], alo[m][0]);
            cvt_split(fb[cur][m][1], ahi[m][1], alo[m][1]);
            cvt_split(fb[cur][m][2], ahi[m][2], alo[m][2]);
            cvt_split(fb[cur][m][3], ahi[m][3], alo[m][3]);
        }

        const int kb = ks * 16;
        #pragma unroll
        for (int n = 0; n < 8; ++n) {
            const int boff = (n * 8 + rq) * BSTRIDE + kb + cq;
            const uint32_t bh0 = *reinterpret_cast<const uint32_t*>(Bhi + boff);
            const uint32_t bh1 = *reinterpret_cast<const uint32_t*>(Bhi + boff + 8);
            const uint32_t bl0 = *reinterpret_cast<const uint32_t*>(Blo + boff);
            const uint32_t bl1 = *reinterpret_cast<const uint32_t*>(Blo + boff + 8);

            #pragma unroll
            for (int m = 0; m < 2; ++m) {
                MMA_BF16(acc[m][n][0], acc[m][n][1], acc[m][n][2], acc[m][n][3],
                         ahi[m][0], ahi[m][1], ahi[m][2], ahi[m][3], bh0, bh1);
                MMA_BF16(acc[m][n][0], acc[m][n][1], acc[m][n][2], acc[m][n][3],
                         ahi[m][0], ahi[m][1], ahi[m][2], ahi[m][3], bl0, bl1);
                MMA_BF16(acc[m][n][0], acc[m][n][1], acc[m][n][2], acc[m][n][3],
                         alo[m][0], alo[m][1], alo[m][2], alo[m][3], bh0, bh1);
            }
        }
    }

    const uint64_t pol = mk_evict_last_policy();
    #pragma unroll
    for (int m = 0; m < 2; ++m) {
        const int r0 = rbase + m * 16 + rq;
        const int r1 = r0 + 8;
        #pragma unroll
        for (int n = 0; n < 8; ++n) {
            const int col = n * 8 + cq;
            if (r0 < NROWS)
                stg_f2_resident(H + (size_t)r0 * HID + col,
                                make_float2(acc[m][n][0], acc[m][n][1]), pol);
            if (r1 < NROWS)
                stg_f2_resident(H + (size_t)r1 * HID + col,
                                make_float2(acc[m][n][2], acc[m][n][3]), pol);
        }
    }
}

// ---------------------------------------------------------------------------
// Kernel 2 (fused): O = relu(A @ H) @ W2
// 4 rows per warp; metadata streaming; O stores pinned (evict_last).
// ---------------------------------------------------------------------------
__global__ void __launch_bounds__(256) spmm_relu_gemm2_kernel(
    const float* __restrict__ H, const float* __restrict__ W2,
    const float* __restrict__ vals, const int* __restrict__ rowptr,
    const int* __restrict__ colind, float* __restrict__ O)
{
    __shared__ float W2s[HID * OUTD];     // 16KB
    __shared__ float Hs[8][4][HID];       // 8KB

    const int tid = threadIdx.x;
    {
        const float4* src = reinterpret_cast<const float4*>(W2);
        float4* dst = reinterpret_cast<float4*>(W2s);
        #pragma unroll
        for (int i = tid; i < (HID * OUTD) / 4; i += 256) dst[i] = src[i];
    }
    __syncthreads();

    const int warp = tid >> 5;
    const int lane = tid & 31;
    const int row0 = (blockIdx.x * 8 + warp) * 4;
    if (row0 >= NROWS) return;

    const int s0   = rowptr[row0];
    const int send = rowptr[min(row0 + 4, NROWS)];
    const int nedg = send - s0;

    float ax[4] = {0.f, 0.f, 0.f, 0.f};
    float ay[4] = {0.f, 0.f, 0.f, 0.f};
    int nrows = 4;

    if (nedg == 64) {
        const int   c_a = __ldcs(colind + s0 + lane);
        const float v_a = __ldcs(vals + s0 + lane);
        const int   c_b = __ldcs(colind + s0 + 32 + lane);
        const float v_b = __ldcs(vals + s0 + 32 + lane);
        #pragma unroll
        for (int e = 0; e < 16; ++e) {
            const int   c0 = __shfl_sync(0xffffffffu, c_a, e);
            const float v0 = __shfl_sync(0xffffffffu, v_a, e);
            const int   c1 = __shfl_sync(0xffffffffu, c_a, 16 + e);
            const float v1 = __shfl_sync(0xffffffffu, v_a, 16 + e);
            const int   c2 = __shfl_sync(0xffffffffu, c_b, e);
            const float v2 = __shfl_sync(0xffffffffu, v_b, e);
            const int   c3 = __shfl_sync(0xffffffffu, c_b, 16 + e);
            const float v3 = __shfl_sync(0xffffffffu, v_b, 16 + e);
            const float2 h0 =
                *reinterpret_cast<const float2*>(H + (size_t)c0 * HID + 2 * lane);
            const float2 h1 =
                *reinterpret_cast<const float2*>(H + (size_t)c1 * HID + 2 * lane);
            const float2 h2 =
                *reinterpret_cast<const float2*>(H + (size_t)c2 * HID + 2 * lane);
            const float2 h3 =
                *reinterpret_cast<const float2*>(H + (size_t)c3 * HID + 2 * lane);
            ax[0] += v0 * h0.x;  ay[0] += v0 * h0.y;
            ax[1] += v1 * h1.x;  ay[1] += v1 * h1.y;
            ax[2] += v2 * h2.x;  ay[2] += v2 * h2.y;
            ax[3] += v3 * h3.x;  ay[3] += v3 * h3.y;
        }
    } else {
        nrows = min(4, NROWS - row0);
        for (int r = 0; r < nrows; ++r) {
            const int row = row0 + r;
            for (int e = rowptr[row]; e < rowptr[row + 1]; ++e) {
                const int   col = colind[e];
                const float v   = vals[e];
                const float2 h  =
                    *reinterpret_cast<const float2*>(H + (size_t)col * HID + 2 * lane);
                ax[r] += v * h.x;  ay[r] += v * h.y;
            }
        }
    }

    #pragma unroll
    for (int r = 0; r < 4; ++r) {
        Hs[warp][r][2 * lane]     = fmaxf(ax[r], 0.f);
        Hs[warp][r][2 * lane + 1] = fmaxf(ay[r], 0.f);
    }
    __syncwarp();

    float ox[4] = {0.f, 0.f, 0.f, 0.f};
    float oy[4] = {0.f, 0.f, 0.f, 0.f};
    #pragma unroll
    for (int j = 0; j < HID; ++j) {
        const float2 w =
            *reinterpret_cast<const float2*>(W2s + j * OUTD + 2 * lane);
        #pragma unroll
        for (int r = 0; r < 4; ++r) {
            const float a = Hs[warp][r][j];
            ox[r] += a * w.x;  oy[r] += a * w.y;
        }
    }

    const uint64_t pol = mk_evict_last_policy();
    #pragma unroll
    for (int r = 0; r < 4; ++r) {
        if (r < nrows)
            stg_f2_resident(O + (size_t)(row0 + r) * OUTD + 2 * lane,
                            make_float2(ox[r], oy[r]), pol);
    }
}

// ---------------------------------------------------------------------------
// Kernel 3: out = A @ O   (4 rows per warp; metadata streaming)
// ---------------------------------------------------------------------------
__global__ void __launch_bounds__(256) spmm2_kernel(
    const float* __restrict__ O, const float* __restrict__ vals,
    const int* __restrict__ rowptr, const int* __restrict__ colind,
    float* __restrict__ out)
{
    const int tid  = threadIdx.x;
    const int warp = tid >> 5;
    const int lane = tid & 31;
    const int row0 = (blockIdx.x * 8 + warp) * 4;
    if (row0 >= NROWS) return;

    const int s0   = rowptr[row0];
    const int send = rowptr[min(row0 + 4, NROWS)];
    const int nedg = send - s0;

    float ax[4] = {0.f, 0.f, 0.f, 0.f};
    float ay[4] = {0.f, 0.f, 0.f, 0.f};

    if (nedg == 64) {
        const int   c_a = __ldcs(colind + s0 + lane);
        const float v_a = __ldcs(vals + s0 + lane);
        const int   c_b = __ldcs(colind + s0 + 32 + lane);
        const float v_b = __ldcs(vals + s0 + 32 + lane);
        #pragma unroll
        for (int e = 0; e < 16; ++e) {
            const int   c0 = __shfl_sync(0xffffffffu, c_a, e);
            const float v0 = __shfl_sync(0xffffffffu, v_a, e);
            const int   c1 = __shfl_sync(0xffffffffu, c_a, 16 + e);
            const float v1 = __shfl_sync(0xffffffffu, v_a, 16 + e);
            const int   c2 = __shfl_sync(0xffffffffu, c_b, e);
            const float v2 = __shfl_sync(0xffffffffu, v_b, e);
            const int   c3 = __shfl_sync(0xffffffffu, c_b, 16 + e);
            const float v3 = __shfl_sync(0xffffffffu, v_b, 16 + e);
            const float2 o0 =
                *reinterpret_cast<const float2*>(O + (size_t)c0 * OUTD + 2 * lane);
            const float2 o1 =
                *reinterpret_cast<const float2*>(O + (size_t)c1 * OUTD + 2 * lane);
            const float2 o2 =
                *reinterpret_cast<const float2*>(O + (size_t)c2 * OUTD + 2 * lane);
            const float2 o3 =
                *reinterpret_cast<const float2*>(O + (size_t)c3 * OUTD + 2 * lane);
            ax[0] += v0 * o0.x;  ay[0] += v0 * o0.y;
            ax[1] += v1 * o1.x;  ay[1] += v1 * o1.y;
            ax[2] += v2 * o2.x;  ay[2] += v2 * o2.y;
            ax[3] += v3 * o3.x;  ay[3] += v3 * o3.y;
        }
        #pragma unroll
        for (int r = 0; r < 4; ++r)
            *reinterpret_cast<float2*>(out + (size_t)(row0 + r) * OUTD + 2 * lane) =
                make_float2(ax[r], ay[r]);
    } else {
        for (int r = 0; r < 4; ++r) {
            const int row = row0 + r;
            if (row >= NROWS) break;
            float bx = 0.f, by = 0.f;
            for (int e = rowptr[row]; e < rowptr[row + 1]; ++e) {
                const int   col = colind[e];
                const float v   = vals[e];
                const float2 o  =
                    *reinterpret_cast<const float2*>(O + (size_t)col * OUTD + 2 * lane);
                bx += v * o.x;  by += v * o.y;
            }
            *reinterpret_cast<float2*>(out + (size_t)row * OUTD + 2 * lane) =
                make_float2(bx, by);
        }
    }
}

// ---------------------------------------------------------------------------
extern "C" void kernel_launch(void* const* d_in, const int* in_sizes, int n_in,
                              void* d_out, int out_size)
{
    const float* X      = (const float*)d_in[0];
    const float* W1     = (const float*)d_in[1];
    const float* W2     = (const float*)d_in[2];
    const float* vals   = (const float*)d_in[3];
    const int*   rowptr = (const int*)d_in[4];
    const int*   colind = (const int*)d_in[5];
    float*       out    = (float*)d_out;

    float* H; cudaGetSymbolAddress((void**)&H, g_H);
    float* O; cudaGetSymbolAddress((void**)&O, g_O);

    const int smem1 = 2 * 64 * BSTRIDE * sizeof(__nv_bfloat16);  // 67584 B
    static bool attr_set = false;
    if (!attr_set) {
        cudaFuncSetAttribute(gemm1_mma_kernel,
                             cudaFuncAttributeMaxDynamicSharedMemorySize, smem1);
        attr_set = true;
    }

    gemm1_mma_kernel<<<(NROWS + 255) / 256, 256, smem1>>>(X, W1, H);
    spmm_relu_gemm2_kernel<<<(NROWS + 31) / 32, 256>>>(H, W2, vals, rowptr,
                                                       colind, O);
    spmm2_kernel<<<(NROWS + 31) / 32, 256>>>(O, vals, rowptr, colind, out);
}

// round 14
// speedup vs baseline: 1.1146x; 1.1146x over previous
#include <cuda_runtime.h>
#include <cuda_bf16.h>
#include <cuda_fp16.h>
#include <cstdint>

#define NROWS 100000
#define INDIM 256
#define HID   64
#define OUTD  64

// scratch (device globals: no allocation allowed) — fp16 to halve gather bytes
// (fp16, not bf16: 10-bit mantissa keeps aggregate rel_err ~1e-4, vs bf16's
//  7-bit which measured 1.15e-3 > threshold in round 13)
__device__ __align__(16) __half g_H[(size_t)NROWS * HID];
__device__ __align__(16) __half g_O[(size_t)NROWS * OUTD];

// m16n8k16 bf16 MMA, f32 accumulate (baseline PTX, works on .target sm_103)
#define MMA_BF16(c0, c1, c2, c3, a0, a1, a2, a3, b0, b1)                      \
    asm volatile(                                                             \
        "mma.sync.aligned.m16n8k16.row.col.f32.bf16.bf16.f32 "                \
        "{%0,%1,%2,%3}, {%4,%5,%6,%7}, {%8,%9}, {%0,%1,%2,%3};"               \
        : "+f"(c0), "+f"(c1), "+f"(c2), "+f"(c3)                              \
        : "r"(a0), "r"(a1), "r"(a2), "r"(a3), "r"(b0), "r"(b1))

// pack two floats into fp16x2 (lo = x, hi = y)
__device__ __forceinline__ uint32_t pack_f16x2(float x, float y) {
    const __half2 h = __floats2half2_rn(x, y);
    return *reinterpret_cast<const uint32_t*>(&h);
}
// unpack fp16x2 to float2
__device__ __forceinline__ float2 unpack_f16x2(uint32_t p) {
    const __half2 h = *reinterpret_cast<const __half2*>(&p);
    return __half22float2(h);
}

// split a float2 into packed bf16x2 hi + bf16x2 lo (residual) — gemm1 input
__device__ __forceinline__ void cvt_split(float2 v, uint32_t& hi, uint32_t& lo) {
    uint32_t h;
    asm("cvt.rn.bf16x2.f32 %0, %1, %2;" : "=r"(h) : "f"(v.y), "f"(v.x));
    const float h0 = __uint_as_float(h << 16);
    const float h1 = __uint_as_float(h & 0xffff0000u);
    const float r0 = v.x - h0;
    const float r1 = v.y - h1;
    uint32_t l;
    asm("cvt.rn.bf16x2.f32 %0, %1, %2;" : "=r"(l) : "f"(r1), "f"(r0));
    hi = h;
    lo = l;
}

#define BSTRIDE 264   // 256 + 8 bf16 padding -> conflict-free B-fragment LDS

// ---------------------------------------------------------------------------
// Kernel 1: H = X @ W1 via warp-level bf16 MMA, split-2 (3 MMAs), f32 accum.
// Round-10 structure; epilogue stores fp16x2.
// ---------------------------------------------------------------------------
__global__ void __launch_bounds__(256, 2) gemm1_mma_kernel(
    const float* __restrict__ X, const float* __restrict__ W1,
    __half* __restrict__ H)
{
    extern __shared__ __nv_bfloat16 wsm[];
    __nv_bfloat16* Bhi = wsm;                 // [64][BSTRIDE]
    __nv_bfloat16* Blo = wsm + 64 * BSTRIDE;  // [64][BSTRIDE]

    const int tid = threadIdx.x;

    for (int idx = tid; idx < INDIM * HID; idx += 256) {
        const int k = idx >> 6;
        const int n = idx & 63;
        const float w = W1[idx];
        const __nv_bfloat16 hb = __float2bfloat16(w);
        const float hf = __bfloat162float(hb);
        Bhi[n * BSTRIDE + k] = hb;
        Blo[n * BSTRIDE + k] = __float2bfloat16(w - hf);
    }
    __syncthreads();

    const int warp  = tid >> 5;
    const int lane  = tid & 31;
    const int rbase = blockIdx.x * 256 + warp * 32;
    if (rbase >= NROWS) return;

    const int rq = lane >> 2;
    const int cq = (lane & 3) * 2;

    const int r00 = rbase + rq;
    const int r01 = r00 + 8;
    const int r10 = rbase + 16 + rq;
    const int r11 = r10 + 8;
    const float* px[2][2];
    px[0][0] = X + (size_t)min(r00, NROWS - 1) * INDIM;
    px[0][1] = X + (size_t)min(r01, NROWS - 1) * INDIM;
    px[1][0] = X + (size_t)min(r10, NROWS - 1) * INDIM;
    px[1][1] = X + (size_t)min(r11, NROWS - 1) * INDIM;

    float acc[2][8][4];
    #pragma unroll
    for (int m = 0; m < 2; ++m)
        #pragma unroll
        for (int n = 0; n < 8; ++n)
            #pragma unroll
            for (int i = 0; i < 4; ++i) acc[m][n][i] = 0.f;

    float2 fb[2][2][4];

    #pragma unroll
    for (int m = 0; m < 2; ++m) {
        fb[0][m][0] = *reinterpret_cast<const float2*>(px[m][0] + cq);
        fb[0][m][1] = *reinterpret_cast<const float2*>(px[m][1] + cq);
        fb[0][m][2] = *reinterpret_cast<const float2*>(px[m][0] + cq + 8);
        fb[0][m][3] = *reinterpret_cast<const float2*>(px[m][1] + cq + 8);
    }

    #pragma unroll
    for (int ks = 0; ks < 16; ++ks) {
        const int cur = ks & 1;
        if (ks < 15) {
            const int kb = (ks + 1) * 16;
            #pragma unroll
            for (int m = 0; m < 2; ++m) {
                fb[cur ^ 1][m][0] = *reinterpret_cast<const float2*>(px[m][0] + kb + cq);
                fb[cur ^ 1][m][1] = *reinterpret_cast<const float2*>(px[m][1] + kb + cq);
                fb[cur ^ 1][m][2] = *reinterpret_cast<const float2*>(px[m][0] + kb + cq + 8);
                fb[cur ^ 1][m][3] = *reinterpret_cast<const float2*>(px[m][1] + kb + cq + 8);
            }
        }

        uint32_t ahi[2][4], alo[2][4];
        #pragma unroll
        for (int m = 0; m < 2; ++m) {
            cvt_split(fb[cur][m][0], ahi[m][0], alo[m][0]);
            cvt_split(fb[cur][m][1], ahi[m][1], alo[m][1]);
            cvt_split(fb[cur][m][2], ahi[m][2], alo[m][2]);
            cvt_split(fb[cur][m][3], ahi[m][3], alo[m][3]);
        }

        const int kb = ks * 16;
        #pragma unroll
        for (int n = 0; n < 8; ++n) {
            const int boff = (n * 8 + rq) * BSTRIDE + kb + cq;
            const uint32_t bh0 = *reinterpret_cast<const uint32_t*>(Bhi + boff);
            const uint32_t bh1 = *reinterpret_cast<const uint32_t*>(Bhi + boff + 8);
            const uint32_t bl0 = *reinterpret_cast<const uint32_t*>(Blo + boff);
            const uint32_t bl1 = *reinterpret_cast<const uint32_t*>(Blo + boff + 8);

            #pragma unroll
            for (int m = 0; m < 2; ++m) {
                MMA_BF16(acc[m][n][0], acc[m][n][1], acc[m][n][2], acc[m][n][3],
                         ahi[m][0], ahi[m][1], ahi[m][2], ahi[m][3], bh0, bh1);
                MMA_BF16(acc[m][n][0], acc[m][n][1], acc[m][n][2], acc[m][n][3],
                         ahi[m][0], ahi[m][1], ahi[m][2], ahi[m][3], bl0, bl1);
                MMA_BF16(acc[m][n][0], acc[m][n][1], acc[m][n][2], acc[m][n][3],
                         alo[m][0], alo[m][1], alo[m][2], alo[m][3], bh0, bh1);
            }
        }
    }

    #pragma unroll
    for (int m = 0; m < 2; ++m) {
        const int r0 = rbase + m * 16 + rq;
        const int r1 = r0 + 8;
        #pragma unroll
        for (int n = 0; n < 8; ++n) {
            const int col = n * 8 + cq;
            if (r0 < NROWS)
                *reinterpret_cast<uint32_t*>(H + (size_t)r0 * HID + col) =
                    pack_f16x2(acc[m][n][0], acc[m][n][1]);
            if (r1 < NROWS)
                *reinterpret_cast<uint32_t*>(H + (size_t)r1 * HID + col) =
                    pack_f16x2(acc[m][n][2], acc[m][n][3]);
        }
    }
}

// ---------------------------------------------------------------------------
// Kernel 2 (fused): O = relu(A @ H) @ W2
// 4 rows per warp; H gathered as fp16x2 (128 B/row), fp32 accumulate.
// ---------------------------------------------------------------------------
__global__ void __launch_bounds__(256) spmm_relu_gemm2_kernel(
    const __half* __restrict__ H, const float* __restrict__ W2,
    const float* __restrict__ vals, const int* __restrict__ rowptr,
    const int* __restrict__ colind, __half* __restrict__ O)
{
    __shared__ float W2s[HID * OUTD];     // 16KB
    __shared__ float Hs[8][4][HID];       // 8KB

    const int tid = threadIdx.x;
    {
        const float4* src = reinterpret_cast<const float4*>(W2);
        float4* dst = reinterpret_cast<float4*>(W2s);
        #pragma unroll
        for (int i = tid; i < (HID * OUTD) / 4; i += 256) dst[i] = src[i];
    }
    __syncthreads();

    const int warp = tid >> 5;
    const int lane = tid & 31;
    const int row0 = (blockIdx.x * 8 + warp) * 4;
    if (row0 >= NROWS) return;

    const int s0   = rowptr[row0];
    const int send = rowptr[min(row0 + 4, NROWS)];
    const int nedg = send - s0;

    float ax[4] = {0.f, 0.f, 0.f, 0.f};
    float ay[4] = {0.f, 0.f, 0.f, 0.f};
    int nrows = 4;

    if (nedg == 64) {
        const int   c_a = __ldg(colind + s0 + lane);
        const float v_a = __ldg(vals + s0 + lane);
        const int   c_b = __ldg(colind + s0 + 32 + lane);
        const float v_b = __ldg(vals + s0 + 32 + lane);
        #pragma unroll
        for (int e = 0; e < 16; ++e) {
            const int   c0 = __shfl_sync(0xffffffffu, c_a, e);
            const float v0 = __shfl_sync(0xffffffffu, v_a, e);
            const int   c1 = __shfl_sync(0xffffffffu, c_a, 16 + e);
            const float v1 = __shfl_sync(0xffffffffu, v_a, 16 + e);
            const int   c2 = __shfl_sync(0xffffffffu, c_b, e);
            const float v2 = __shfl_sync(0xffffffffu, v_b, e);
            const int   c3 = __shfl_sync(0xffffffffu, c_b, 16 + e);
            const float v3 = __shfl_sync(0xffffffffu, v_b, 16 + e);
            const float2 h0 = unpack_f16x2(
                *reinterpret_cast<const uint32_t*>(H + (size_t)c0 * HID + 2 * lane));
            const float2 h1 = unpack_f16x2(
                *reinterpret_cast<const uint32_t*>(H + (size_t)c1 * HID + 2 * lane));
            const float2 h2 = unpack_f16x2(
                *reinterpret_cast<const uint32_t*>(H + (size_t)c2 * HID + 2 * lane));
            const float2 h3 = unpack_f16x2(
                *reinterpret_cast<const uint32_t*>(H + (size_t)c3 * HID + 2 * lane));
            ax[0] += v0 * h0.x;  ay[0] += v0 * h0.y;
            ax[1] += v1 * h1.x;  ay[1] += v1 * h1.y;
            ax[2] += v2 * h2.x;  ay[2] += v2 * h2.y;
            ax[3] += v3 * h3.x;  ay[3] += v3 * h3.y;
        }
    } else {
        nrows = min(4, NROWS - row0);
        for (int r = 0; r < nrows; ++r) {
            const int row = row0 + r;
            for (int e = rowptr[row]; e < rowptr[row + 1]; ++e) {
                const int   col = colind[e];
                const float v   = vals[e];
                const float2 h  = unpack_f16x2(
                    *reinterpret_cast<const uint32_t*>(H + (size_t)col * HID + 2 * lane));
                ax[r] += v * h.x;  ay[r] += v * h.y;
            }
        }
    }

    #pragma unroll
    for (int r = 0; r < 4; ++r) {
        Hs[warp][r][2 * lane]     = fmaxf(ax[r], 0.f);
        Hs[warp][r][2 * lane + 1] = fmaxf(ay[r], 0.f);
    }
    __syncwarp();

    float ox[4] = {0.f, 0.f, 0.f, 0.f};
    float oy[4] = {0.f, 0.f, 0.f, 0.f};
    #pragma unroll
    for (int j = 0; j < HID; ++j) {
        const float2 w =
            *reinterpret_cast<const float2*>(W2s + j * OUTD + 2 * lane);
        #pragma unroll
        for (int r = 0; r < 4; ++r) {
            const float a = Hs[warp][r][j];
            ox[r] += a * w.x;  oy[r] += a * w.y;
        }
    }

    #pragma unroll
    for (int r = 0; r < 4; ++r) {
        if (r < nrows)
            *reinterpret_cast<uint32_t*>(O + (size_t)(row0 + r) * OUTD + 2 * lane) =
                pack_f16x2(ox[r], oy[r]);
    }
}

// ---------------------------------------------------------------------------
// Kernel 3: out = A @ O   (4 rows per warp; O gathered as fp16x2)
// ---------------------------------------------------------------------------
__global__ void __launch_bounds__(256) spmm2_kernel(
    const __half* __restrict__ O, const float* __restrict__ vals,
    const int* __restrict__ rowptr, const int* __restrict__ colind,
    float* __restrict__ out)
{
    const int tid  = threadIdx.x;
    const int warp = tid >> 5;
    const int lane = tid & 31;
    const int row0 = (blockIdx.x * 8 + warp) * 4;
    if (row0 >= NROWS) return;

    const int s0   = rowptr[row0];
    const int send = rowptr[min(row0 + 4, NROWS)];
    const int nedg = send - s0;

    float ax[4] = {0.f, 0.f, 0.f, 0.f};
    float ay[4] = {0.f, 0.f, 0.f, 0.f};

    if (nedg == 64) {
        const int   c_a = __ldg(colind + s0 + lane);
        const float v_a = __ldg(vals + s0 + lane);
        const int   c_b = __ldg(colind + s0 + 32 + lane);
        const float v_b = __ldg(vals + s0 + 32 + lane);
        #pragma unroll
        for (int e = 0; e < 16; ++e) {
            const int   c0 = __shfl_sync(0xffffffffu, c_a, e);
            const float v0 = __shfl_sync(0xffffffffu, v_a, e);
            const int   c1 = __shfl_sync(0xffffffffu, c_a, 16 + e);
            const float v1 = __shfl_sync(0xffffffffu, v_a, 16 + e);
            const int   c2 = __shfl_sync(0xffffffffu, c_b, e);
            const float v2 = __shfl_sync(0xffffffffu, v_b, e);
            const int   c3 = __shfl_sync(0xffffffffu, c_b, 16 + e);
            const float v3 = __shfl_sync(0xffffffffu, v_b, 16 + e);
            const float2 o0 = unpack_f16x2(
                *reinterpret_cast<const uint32_t*>(O + (size_t)c0 * OUTD + 2 * lane));
            const float2 o1 = unpack_f16x2(
                *reinterpret_cast<const uint32_t*>(O + (size_t)c1 * OUTD + 2 * lane));
            const float2 o2 = unpack_f16x2(
                *reinterpret_cast<const uint32_t*>(O + (size_t)c2 * OUTD + 2 * lane));
            const float2 o3 = unpack_f16x2(
                *reinterpret_cast<const uint32_t*>(O + (size_t)c3 * OUTD + 2 * lane));
            ax[0] += v0 * o0.x;  ay[0] += v0 * o0.y;
            ax[1] += v1 * o1.x;  ay[1] += v1 * o1.y;
            ax[2] += v2 * o2.x;  ay[2] += v2 * o2.y;
            ax[3] += v3 * o3.x;  ay[3] += v3 * o3.y;
        }
        #pragma unroll
        for (int r = 0; r < 4; ++r)
            *reinterpret_cast<float2*>(out + (size_t)(row0 + r) * OUTD + 2 * lane) =
                make_float2(ax[r], ay[r]);
    } else {
        for (int r = 0; r < 4; ++r) {
            const int row = row0 + r;
            if (row >= NROWS) break;
            float bx = 0.f, by = 0.f;
            for (int e = rowptr[row]; e < rowptr[row + 1]; ++e) {
                const int   col = colind[e];
                const float v   = vals[e];
                const float2 o  = unpack_f16x2(
                    *reinterpret_cast<const uint32_t*>(O + (size_t)col * OUTD + 2 * lane));
                bx += v * o.x;  by += v * o.y;
            }
            *reinterpret_cast<float2*>(out + (size_t)row * OUTD + 2 * lane) =
                make_float2(bx, by);
        }
    }
}

// ---------------------------------------------------------------------------
extern "C" void kernel_launch(void* const* d_in, const int* in_sizes, int n_in,
                              void* d_out, int out_size)
{
    const float* X      = (const float*)d_in[0];
    const float* W1     = (const float*)d_in[1];
    const float* W2     = (const float*)d_in[2];
    const float* vals   = (const float*)d_in[3];
    const int*   rowptr = (const int*)d_in[4];
    const int*   colind = (const int*)d_in[5];
    float*       out    = (float*)d_out;

    __half* H; cudaGetSymbolAddress((void**)&H, g_H);
    __half* O; cudaGetSymbolAddress((void**)&O, g_O);

    const int smem1 = 2 * 64 * BSTRIDE * sizeof(__nv_bfloat16);  // 67584 B
    static bool attr_set = false;
    if (!attr_set) {
        cudaFuncSetAttribute(gemm1_mma_kernel,
                             cudaFuncAttributeMaxDynamicSharedMemorySize, smem1);
        attr_set = true;
    }

    gemm1_mma_kernel<<<(NROWS + 255) / 256, 256, smem1>>>(X, W1, H);
    spmm_relu_gemm2_kernel<<<(NROWS + 31) / 32, 256>>>(H, W2, vals, rowptr,
                                                       colind, O);
    spmm2_kernel<<<(NROWS + 31) / 32, 256>>>(O, vals, rowptr, colind, out);
}

// round 15
// speedup vs baseline: 1.1372x; 1.0203x over previous
#include <cuda_runtime.h>
#include <cuda_bf16.h>
#include <cuda_fp16.h>
#include <cstdint>

#define NROWS 100000
#define INDIM 256
#define HID   64
#define OUTD  64

// scratch (device globals: no allocation allowed) — fp16 halves gather bytes
__device__ __align__(16) __half g_H[(size_t)NROWS * HID];
__device__ __align__(16) __half g_O[(size_t)NROWS * OUTD];

// m16n8k16 bf16 MMA, f32 accumulate (baseline PTX, works on .target sm_103)
#define MMA_BF16(c0, c1, c2, c3, a0, a1, a2, a3, b0, b1)                      \
    asm volatile(                                                             \
        "mma.sync.aligned.m16n8k16.row.col.f32.bf16.bf16.f32 "                \
        "{%0,%1,%2,%3}, {%4,%5,%6,%7}, {%8,%9}, {%0,%1,%2,%3};"               \
        : "+f"(c0), "+f"(c1), "+f"(c2), "+f"(c3)                              \
        : "r"(a0), "r"(a1), "r"(a2), "r"(a3), "r"(b0), "r"(b1))

#define CP_ASYNC16(dst_u32, src_ptr)                                          \
    asm volatile("cp.async.cg.shared.global [%0], [%1], 16;"                  \
                 :: "r"(dst_u32), "l"(src_ptr))
#define CP_COMMIT()  asm volatile("cp.async.commit_group;")
#define CP_WAIT1()   asm volatile("cp.async.wait_group 1;")

__device__ __forceinline__ uint32_t pack_f16x2(float x, float y) {
    const __half2 h = __floats2half2_rn(x, y);
    return *reinterpret_cast<const uint32_t*>(&h);
}
__device__ __forceinline__ float2 unpack_f16x2(uint32_t p) {
    const __half2 h = *reinterpret_cast<const __half2*>(&p);
    return __half22float2(h);
}
__device__ __forceinline__ void cvt_split(float2 v, uint32_t& hi, uint32_t& lo) {
    uint32_t h;
    asm("cvt.rn.bf16x2.f32 %0, %1, %2;" : "=r"(h) : "f"(v.y), "f"(v.x));
    const float h0 = __uint_as_float(h << 16);
    const float h1 = __uint_as_float(h & 0xffff0000u);
    const float r0 = v.x - h0;
    const float r1 = v.y - h1;
    uint32_t l;
    asm("cvt.rn.bf16x2.f32 %0, %1, %2;" : "=r"(l) : "f"(r1), "f"(r0));
    hi = h;
    lo = l;
}

#define BSTRIDE 264         // B tiles: 256 + 8 bf16 padding, conflict-free
#define BBYTES  (2 * 64 * BSTRIDE * 2)   // 67584
#define XSTAGEF 4096        // floats per X stage (256 rows x 16 cols)
#define SMEM1   (BBYTES + 2 * XSTAGEF * 4)   // 100352 B

// X smem offset (floats) with 16B-chunk XOR swizzle: conflict-free frags
__device__ __forceinline__ int xs_off(int row, int col) {
    return row * 16 + ((((col >> 2) ^ row) & 3) << 2) + (col & 3);
}

// ---------------------------------------------------------------------------
// Kernel 1: H = X @ W1 via bf16 MMA split-2 (3 MMAs), fp32 accumulate.
// X staged via cp.async depth-2 pipeline (register-free MLP); fragments from
// swizzled smem. B (W1 hi/lo) in smem as before. fp16 H output.
// ---------------------------------------------------------------------------
__global__ void __launch_bounds__(256, 2) gemm1_mma_kernel(
    const float* __restrict__ X, const float* __restrict__ W1,
    __half* __restrict__ H)
{
    extern __shared__ char sraw[];
    __nv_bfloat16* Bhi = reinterpret_cast<__nv_bfloat16*>(sraw);
    __nv_bfloat16* Blo = Bhi + 64 * BSTRIDE;
    float* Xst = reinterpret_cast<float*>(sraw + BBYTES);
    const uint32_t xbase = (uint32_t)__cvta_generic_to_shared(Xst);

    const int tid  = threadIdx.x;
    const int warp = tid >> 5;
    const int lane = tid & 31;
    const int rbase_blk = blockIdx.x * 256;

    // issue cp.asyncs for k-step ks into stage st (1024 16B chunks / CTA)
    auto issue = [&](int ks, int st) {
        const int kb = ks * 16;
        #pragma unroll
        for (int i = 0; i < 4; ++i) {
            const int idx = tid + i * 256;        // 0..1023
            const int row = idx >> 2;
            const int ch  = idx & 3;
            const int grow = min(rbase_blk + row, NROWS - 1);
            const float* src = X + (size_t)grow * INDIM + kb + ch * 4;
            const uint32_t dst =
                xbase + ((st * XSTAGEF + row * 16 + (((ch ^ row) & 3) << 2)) << 2);
            CP_ASYNC16(dst, src);
        }
        CP_COMMIT();
    };

    issue(0, 0);
    issue(1, 1);

    // convert W1 (k-major [256][64]) -> smem n-major hi/lo
    for (int idx = tid; idx < INDIM * HID; idx += 256) {
        const int k = idx >> 6;
        const int n = idx & 63;
        const float w = W1[idx];
        const __nv_bfloat16 hb = __float2bfloat16(w);
        const float hf = __bfloat162float(hb);
        Bhi[n * BSTRIDE + k] = hb;
        Blo[n * BSTRIDE + k] = __float2bfloat16(w - hf);
    }

    const int rq = lane >> 2;         // 0..7
    const int cq = (lane & 3) * 2;    // 0,2,4,6
    const int lrb = warp * 32;        // local row base within tile

    float acc[2][8][4];
    #pragma unroll
    for (int m = 0; m < 2; ++m)
        #pragma unroll
        for (int n = 0; n < 8; ++n)
            #pragma unroll
            for (int i = 0; i < 4; ++i) acc[m][n][i] = 0.f;

    #pragma unroll 4
    for (int ks = 0; ks < 16; ++ks) {
        CP_WAIT1();          // stage ks data arrived
        __syncthreads();     // visible across CTA (also covers B on ks=0)

        const float* Xs = Xst + (ks & 1) * XSTAGEF;

        uint32_t ahi[2][4], alo[2][4];
        #pragma unroll
        for (int m = 0; m < 2; ++m) {
            const int r0 = lrb + m * 16 + rq;
            const int r1 = r0 + 8;
            const float2 f0 = *reinterpret_cast<const float2*>(Xs + xs_off(r0, cq));
            const float2 f1 = *reinterpret_cast<const float2*>(Xs + xs_off(r1, cq));
            const float2 f2 = *reinterpret_cast<const float2*>(Xs + xs_off(r0, cq + 8));
            const float2 f3 = *reinterpret_cast<const float2*>(Xs + xs_off(r1, cq + 8));
            cvt_split(f0, ahi[m][0], alo[m][0]);
            cvt_split(f1, ahi[m][1], alo[m][1]);
            cvt_split(f2, ahi[m][2], alo[m][2]);
            cvt_split(f3, ahi[m][3], alo[m][3]);
        }

        const int kb = ks * 16;
        #pragma unroll
        for (int n = 0; n < 8; ++n) {
            const int boff = (n * 8 + rq) * BSTRIDE + kb + cq;
            const uint32_t bh0 = *reinterpret_cast<const uint32_t*>(Bhi + boff);
            const uint32_t bh1 = *reinterpret_cast<const uint32_t*>(Bhi + boff + 8);
            const uint32_t bl0 = *reinterpret_cast<const uint32_t*>(Blo + boff);
            const uint32_t bl1 = *reinterpret_cast<const uint32_t*>(Blo + boff + 8);

            #pragma unroll
            for (int m = 0; m < 2; ++m) {
                MMA_BF16(acc[m][n][0], acc[m][n][1], acc[m][n][2], acc[m][n][3],
                         ahi[m][0], ahi[m][1], ahi[m][2], ahi[m][3], bh0, bh1);
                MMA_BF16(acc[m][n][0], acc[m][n][1], acc[m][n][2], acc[m][n][3],
                         ahi[m][0], ahi[m][1], ahi[m][2], ahi[m][3], bl0, bl1);
                MMA_BF16(acc[m][n][0], acc[m][n][1], acc[m][n][2], acc[m][n][3],
                         alo[m][0], alo[m][1], alo[m][2], alo[m][3], bh0, bh1);
            }
        }

        __syncthreads();     // stage ks consumed; safe to overwrite
        if (ks + 2 < 16) issue(ks + 2, ks & 1);
        else             CP_COMMIT();    // keep group-count invariant
    }

    #pragma unroll
    for (int m = 0; m < 2; ++m) {
        const int r0 = rbase_blk + lrb + m * 16 + rq;
        const int r1 = r0 + 8;
        #pragma unroll
        for (int n = 0; n < 8; ++n) {
            const int col = n * 8 + cq;
            if (r0 < NROWS)
                *reinterpret_cast<uint32_t*>(H + (size_t)r0 * HID + col) =
                    pack_f16x2(acc[m][n][0], acc[m][n][1]);
            if (r1 < NROWS)
                *reinterpret_cast<uint32_t*>(H + (size_t)r1 * HID + col) =
                    pack_f16x2(acc[m][n][2], acc[m][n][3]);
        }
    }
}

// ---------------------------------------------------------------------------
// Kernel 2 (fused): O = relu(A @ H) @ W2   — unchanged round-14 winner
// ---------------------------------------------------------------------------
__global__ void __launch_bounds__(256) spmm_relu_gemm2_kernel(
    const __half* __restrict__ H, const float* __restrict__ W2,
    const float* __restrict__ vals, const int* __restrict__ rowptr,
    const int* __restrict__ colind, __half* __restrict__ O)
{
    __shared__ float W2s[HID * OUTD];
    __shared__ float Hs[8][4][HID];

    const int tid = threadIdx.x;
    {
        const float4* src = reinterpret_cast<const float4*>(W2);
        float4* dst = reinterpret_cast<float4*>(W2s);
        #pragma unroll
        for (int i = tid; i < (HID * OUTD) / 4; i += 256) dst[i] = src[i];
    }
    __syncthreads();

    const int warp = tid >> 5;
    const int lane = tid & 31;
    const int row0 = (blockIdx.x * 8 + warp) * 4;
    if (row0 >= NROWS) return;

    const int s0   = rowptr[row0];
    const int send = rowptr[min(row0 + 4, NROWS)];
    const int nedg = send - s0;

    float ax[4] = {0.f, 0.f, 0.f, 0.f};
    float ay[4] = {0.f, 0.f, 0.f, 0.f};
    int nrows = 4;

    if (nedg == 64) {
        const int   c_a = __ldg(colind + s0 + lane);
        const float v_a = __ldg(vals + s0 + lane);
        const int   c_b = __ldg(colind + s0 + 32 + lane);
        const float v_b = __ldg(vals + s0 + 32 + lane);
        #pragma unroll
        for (int e = 0; e < 16; ++e) {
            const int   c0 = __shfl_sync(0xffffffffu, c_a, e);
            const float v0 = __shfl_sync(0xffffffffu, v_a, e);
            const int   c1 = __shfl_sync(0xffffffffu, c_a, 16 + e);
            const float v1 = __shfl_sync(0xffffffffu, v_a, 16 + e);
            const int   c2 = __shfl_sync(0xffffffffu, c_b, e);
            const float v2 = __shfl_sync(0xffffffffu, v_b, e);
            const int   c3 = __shfl_sync(0xffffffffu, c_b, 16 + e);
            const float v3 = __shfl_sync(0xffffffffu, v_b, 16 + e);
            const float2 h0 = unpack_f16x2(
                *reinterpret_cast<const uint32_t*>(H + (size_t)c0 * HID + 2 * lane));
            const float2 h1 = unpack_f16x2(
                *reinterpret_cast<const uint32_t*>(H + (size_t)c1 * HID + 2 * lane));
            const float2 h2 = unpack_f16x2(
                *reinterpret_cast<const uint32_t*>(H + (size_t)c2 * HID + 2 * lane));
            const float2 h3 = unpack_f16x2(
                *reinterpret_cast<const uint32_t*>(H + (size_t)c3 * HID + 2 * lane));
            ax[0] += v0 * h0.x;  ay[0] += v0 * h0.y;
            ax[1] += v1 * h1.x;  ay[1] += v1 * h1.y;
            ax[2] += v2 * h2.x;  ay[2] += v2 * h2.y;
            ax[3] += v3 * h3.x;  ay[3] += v3 * h3.y;
        }
    } else {
        nrows = min(4, NROWS - row0);
        for (int r = 0; r < nrows; ++r) {
            const int row = row0 + r;
            for (int e = rowptr[row]; e < rowptr[row + 1]; ++e) {
                const int   col = colind[e];
                const float v   = vals[e];
                const float2 h  = unpack_f16x2(
                    *reinterpret_cast<const uint32_t*>(H + (size_t)col * HID + 2 * lane));
                ax[r] += v * h.x;  ay[r] += v * h.y;
            }
        }
    }

    #pragma unroll
    for (int r = 0; r < 4; ++r) {
        Hs[warp][r][2 * lane]     = fmaxf(ax[r], 0.f);
        Hs[warp][r][2 * lane + 1] = fmaxf(ay[r], 0.f);
    }
    __syncwarp();

    float ox[4] = {0.f, 0.f, 0.f, 0.f};
    float oy[4] = {0.f, 0.f, 0.f, 0.f};
    #pragma unroll
    for (int j = 0; j < HID; ++j) {
        const float2 w =
            *reinterpret_cast<const float2*>(W2s + j * OUTD + 2 * lane);
        #pragma unroll
        for (int r = 0; r < 4; ++r) {
            const float a = Hs[warp][r][j];
            ox[r] += a * w.x;  oy[r] += a * w.y;
        }
    }

    #pragma unroll
    for (int r = 0; r < 4; ++r) {
        if (r < nrows)
            *reinterpret_cast<uint32_t*>(O + (size_t)(row0 + r) * OUTD + 2 * lane) =
                pack_f16x2(ox[r], oy[r]);
    }
}

// ---------------------------------------------------------------------------
// Kernel 3: out = A @ O   — unchanged round-14 winner
// ---------------------------------------------------------------------------
__global__ void __launch_bounds__(256) spmm2_kernel(
    const __half* __restrict__ O, const float* __restrict__ vals,
    const int* __restrict__ rowptr, const int* __restrict__ colind,
    float* __restrict__ out)
{
    const int tid  = threadIdx.x;
    const int warp = tid >> 5;
    const int lane = tid & 31;
    const int row0 = (blockIdx.x * 8 + warp) * 4;
    if (row0 >= NROWS) return;

    const int s0   = rowptr[row0];
    const int send = rowptr[min(row0 + 4, NROWS)];
    const int nedg = send - s0;

    float ax[4] = {0.f, 0.f, 0.f, 0.f};
    float ay[4] = {0.f, 0.f, 0.f, 0.f};

    if (nedg == 64) {
        const int   c_a = __ldg(colind + s0 + lane);
        const float v_a = __ldg(vals + s0 + lane);
        const int   c_b = __ldg(colind + s0 + 32 + lane);
        const float v_b = __ldg(vals + s0 + 32 + lane);
        #pragma unroll
        for (int e = 0; e < 16; ++e) {
            const int   c0 = __shfl_sync(0xffffffffu, c_a, e);
            const float v0 = __shfl_sync(0xffffffffu, v_a, e);
            const int   c1 = __shfl_sync(0xffffffffu, c_a, 16 + e);
            const float v1 = __shfl_sync(0xffffffffu, v_a, 16 + e);
            const int   c2 = __shfl_sync(0xffffffffu, c_b, e);
            const float v2 = __shfl_sync(0xffffffffu, v_b, e);
            const int   c3 = __shfl_sync(0xffffffffu, c_b, 16 + e);
            const float v3 = __shfl_sync(0xffffffffu, v_b, 16 + e);
            const float2 o0 = unpack_f16x2(
                *reinterpret_cast<const uint32_t*>(O + (size_t)c0 * OUTD + 2 * lane));
            const float2 o1 = unpack_f16x2(
                *reinterpret_cast<const uint32_t*>(O + (size_t)c1 * OUTD + 2 * lane));
            const float2 o2 = unpack_f16x2(
                *reinterpret_cast<const uint32_t*>(O + (size_t)c2 * OUTD + 2 * lane));
            const float2 o3 = unpack_f16x2(
                *reinterpret_cast<const uint32_t*>(O + (size_t)c3 * OUTD + 2 * lane));
            ax[0] += v0 * o0.x;  ay[0] += v0 * o0.y;
            ax[1] += v1 * o1.x;  ay[1] += v1 * o1.y;
            ax[2] += v2 * o2.x;  ay[2] += v2 * o2.y;
            ax[3] += v3 * o3.x;  ay[3] += v3 * o3.y;
        }
        #pragma unroll
        for (int r = 0; r < 4; ++r)
            *reinterpret_cast<float2*>(out + (size_t)(row0 + r) * OUTD + 2 * lane) =
                make_float2(ax[r], ay[r]);
    } else {
        for (int r = 0; r < 4; ++r) {
            const int row = row0 + r;
            if (row >= NROWS) break;
            float bx = 0.f, by = 0.f;
            for (int e = rowptr[row]; e < rowptr[row + 1]; ++e) {
                const int   col = colind[e];
                const float v   = vals[e];
                const float2 o  = unpack_f16x2(
                    *reinterpret_cast<const uint32_t*>(O + (size_t)col * OUTD + 2 * lane));
                bx += v * o.x;  by += v * o.y;
            }
            *reinterpret_cast<float2*>(out + (size_t)row * OUTD + 2 * lane) =
                make_float2(bx, by);
        }
    }
}

// ---------------------------------------------------------------------------
extern "C" void kernel_launch(void* const* d_in, const int* in_sizes, int n_in,
                              void* d_out, int out_size)
{
    const float* X      = (const float*)d_in[0];
    const float* W1     = (const float*)d_in[1];
    const float* W2     = (const float*)d_in[2];
    const float* vals   = (const float*)d_in[3];
    const int*   rowptr = (const int*)d_in[4];
    const int*   colind = (const int*)d_in[5];
    float*       out    = (float*)d_out;

    __half* H; cudaGetSymbolAddress((void**)&H, g_H);
    __half* O; cudaGetSymbolAddress((void**)&O, g_O);

    static bool attr_set = false;
    if (!attr_set) {
        cudaFuncSetAttribute(gemm1_mma_kernel,
                             cudaFuncAttributeMaxDynamicSharedMemorySize, SMEM1);
        attr_set = true;
    }

    gemm1_mma_kernel<<<(NROWS + 255) / 256, 256, SMEM1>>>(X, W1, H);
    spmm_relu_gemm2_kernel<<<(NROWS + 31) / 32, 256>>>(H, W2, vals, rowptr,
                                                       colind, O);
    spmm2_kernel<<<(NROWS + 31) / 32, 256>>>(O, vals, rowptr, colind, out);
}

// round 16
// speedup vs baseline: 1.2235x; 1.0759x over previous
#include <cuda_runtime.h>
#include <cuda_fp16.h>
#include <cstdint>

#define NROWS 100000
#define INDIM 256
#define HID   64
#define OUTD  64

// scratch (device globals: no allocation allowed) — fp16 halves gather bytes
__device__ __align__(16) __half g_H[(size_t)NROWS * HID];
__device__ __align__(16) __half g_O[(size_t)NROWS * OUTD];

// m16n8k16 fp16 MMA, f32 accumulate (baseline PTX, works on .target sm_103)
#define MMA_F16(c0, c1, c2, c3, a0, a1, a2, a3, b0, b1)                       \
    asm volatile(                                                             \
        "mma.sync.aligned.m16n8k16.row.col.f32.f16.f16.f32 "                  \
        "{%0,%1,%2,%3}, {%4,%5,%6,%7}, {%8,%9}, {%0,%1,%2,%3};"               \
        : "+f"(c0), "+f"(c1), "+f"(c2), "+f"(c3)                              \
        : "r"(a0), "r"(a1), "r"(a2), "r"(a3), "r"(b0), "r"(b1))

#define CP_ASYNC16(dst_u32, src_ptr)                                          \
    asm volatile("cp.async.cg.shared.global [%0], [%1], 16;"                  \
                 :: "r"(dst_u32), "l"(src_ptr))
#define CP_COMMIT()  asm volatile("cp.async.commit_group;")
#define CP_WAIT1()   asm volatile("cp.async.wait_group 1;")

__device__ __forceinline__ uint32_t pack_f16x2(float x, float y) {
    const __half2 h = __floats2half2_rn(x, y);
    return *reinterpret_cast<const uint32_t*>(&h);
}
__device__ __forceinline__ float2 unpack_f16x2(uint32_t p) {
    const __half2 h = *reinterpret_cast<const __half2*>(&p);
    return __half22float2(h);
}

#define BSTRIDE 264         // B tile: 256 + 8 fp16 padding, conflict-free
#define BBYTES  (64 * BSTRIDE * 2)           // 33792 (single fp16 W tile)
#define XSTAGEF 4096        // floats per X stage (256 rows x 16 cols)
#define SMEM1   (BBYTES + 2 * XSTAGEF * 4)   // 66560 B

// X smem offset (floats) with 16B-chunk XOR swizzle: conflict-free frags
__device__ __forceinline__ int xs_off(int row, int col) {
    return row * 16 + ((((col >> 2) ^ row) & 3) << 2) + (col & 3);
}

// ---------------------------------------------------------------------------
// Kernel 1: H = X @ W1 via single fp16 MMA (16 per warp-kstep), fp32 accum.
// X staged via cp.async depth-2; W1 as one fp16 smem tile; fp16 H output.
// ---------------------------------------------------------------------------
__global__ void __launch_bounds__(256, 2) gemm1_mma_kernel(
    const float* __restrict__ X, const float* __restrict__ W1,
    __half* __restrict__ H)
{
    extern __shared__ char sraw[];
    __half* Bs = reinterpret_cast<__half*>(sraw);          // [64][BSTRIDE]
    float* Xst = reinterpret_cast<float*>(sraw + BBYTES);
    const uint32_t xbase = (uint32_t)__cvta_generic_to_shared(Xst);

    const int tid  = threadIdx.x;
    const int warp = tid >> 5;
    const int lane = tid & 31;
    const int rbase_blk = blockIdx.x * 256;

    auto issue = [&](int ks, int st) {
        const int kb = ks * 16;
        #pragma unroll
        for (int i = 0; i < 4; ++i) {
            const int idx = tid + i * 256;        // 0..1023
            const int row = idx >> 2;
            const int ch  = idx & 3;
            const int grow = min(rbase_blk + row, NROWS - 1);
            const float* src = X + (size_t)grow * INDIM + kb + ch * 4;
            const uint32_t dst =
                xbase + ((st * XSTAGEF + row * 16 + (((ch ^ row) & 3) << 2)) << 2);
            CP_ASYNC16(dst, src);
        }
        CP_COMMIT();
    };

    issue(0, 0);
    issue(1, 1);

    // convert W1 (k-major [256][64]) -> smem n-major fp16
    for (int idx = tid; idx < INDIM * HID; idx += 256) {
        const int k = idx >> 6;
        const int n = idx & 63;
        Bs[n * BSTRIDE + k] = __float2half_rn(W1[idx]);
    }

    const int rq = lane >> 2;         // 0..7
    const int cq = (lane & 3) * 2;    // 0,2,4,6
    const int lrb = warp * 32;        // local row base within tile

    float acc[2][8][4];
    #pragma unroll
    for (int m = 0; m < 2; ++m)
        #pragma unroll
        for (int n = 0; n < 8; ++n)
            #pragma unroll
            for (int i = 0; i < 4; ++i) acc[m][n][i] = 0.f;

    #pragma unroll 4
    for (int ks = 0; ks < 16; ++ks) {
        CP_WAIT1();
        __syncthreads();

        const float* Xs = Xst + (ks & 1) * XSTAGEF;

        uint32_t a[2][4];
        #pragma unroll
        for (int m = 0; m < 2; ++m) {
            const int r0 = lrb + m * 16 + rq;
            const int r1 = r0 + 8;
            const float2 f0 = *reinterpret_cast<const float2*>(Xs + xs_off(r0, cq));
            const float2 f1 = *reinterpret_cast<const float2*>(Xs + xs_off(r1, cq));
            const float2 f2 = *reinterpret_cast<const float2*>(Xs + xs_off(r0, cq + 8));
            const float2 f3 = *reinterpret_cast<const float2*>(Xs + xs_off(r1, cq + 8));
            a[m][0] = pack_f16x2(f0.x, f0.y);
            a[m][1] = pack_f16x2(f1.x, f1.y);
            a[m][2] = pack_f16x2(f2.x, f2.y);
            a[m][3] = pack_f16x2(f3.x, f3.y);
        }

        const int kb = ks * 16;
        #pragma unroll
        for (int n = 0; n < 8; ++n) {
            const int boff = (n * 8 + rq) * BSTRIDE + kb + cq;
            const uint32_t b0 = *reinterpret_cast<const uint32_t*>(Bs + boff);
            const uint32_t b1 = *reinterpret_cast<const uint32_t*>(Bs + boff + 8);

            #pragma unroll
            for (int m = 0; m < 2; ++m) {
                MMA_F16(acc[m][n][0], acc[m][n][1], acc[m][n][2], acc[m][n][3],
                        a[m][0], a[m][1], a[m][2], a[m][3], b0, b1);
            }
        }

        __syncthreads();
        if (ks + 2 < 16) issue(ks + 2, ks & 1);
        else             CP_COMMIT();
    }

    #pragma unroll
    for (int m = 0; m < 2; ++m) {
        const int r0 = rbase_blk + lrb + m * 16 + rq;
        const int r1 = r0 + 8;
        #pragma unroll
        for (int n = 0; n < 8; ++n) {
            const int col = n * 8 + cq;
            if (r0 < NROWS)
                *reinterpret_cast<uint32_t*>(H + (size_t)r0 * HID + col) =
                    pack_f16x2(acc[m][n][0], acc[m][n][1]);
            if (r1 < NROWS)
                *reinterpret_cast<uint32_t*>(H + (size_t)r1 * HID + col) =
                    pack_f16x2(acc[m][n][2], acc[m][n][3]);
        }
    }
}

// ---------------------------------------------------------------------------
// Kernel 2 (fused): O = relu(A @ H) @ W2   — unchanged round-14/15 winner
// ---------------------------------------------------------------------------
__global__ void __launch_bounds__(256) spmm_relu_gemm2_kernel(
    const __half* __restrict__ H, const float* __restrict__ W2,
    const float* __restrict__ vals, const int* __restrict__ rowptr,
    const int* __restrict__ colind, __half* __restrict__ O)
{
    __shared__ float W2s[HID * OUTD];
    __shared__ float Hs[8][4][HID];

    const int tid = threadIdx.x;
    {
        const float4* src = reinterpret_cast<const float4*>(W2);
        float4* dst = reinterpret_cast<float4*>(W2s);
        #pragma unroll
        for (int i = tid; i < (HID * OUTD) / 4; i += 256) dst[i] = src[i];
    }
    __syncthreads();

    const int warp = tid >> 5;
    const int lane = tid & 31;
    const int row0 = (blockIdx.x * 8 + warp) * 4;
    if (row0 >= NROWS) return;

    const int s0   = rowptr[row0];
    const int send = rowptr[min(row0 + 4, NROWS)];
    const int nedg = send - s0;

    float ax[4] = {0.f, 0.f, 0.f, 0.f};
    float ay[4] = {0.f, 0.f, 0.f, 0.f};
    int nrows = 4;

    if (nedg == 64) {
        const int   c_a = __ldg(colind + s0 + lane);
        const float v_a = __ldg(vals + s0 + lane);
        const int   c_b = __ldg(colind + s0 + 32 + lane);
        const float v_b = __ldg(vals + s0 + 32 + lane);
        #pragma unroll
        for (int e = 0; e < 16; ++e) {
            const int   c0 = __shfl_sync(0xffffffffu, c_a, e);
            const float v0 = __shfl_sync(0xffffffffu, v_a, e);
            const int   c1 = __shfl_sync(0xffffffffu, c_a, 16 + e);
            const float v1 = __shfl_sync(0xffffffffu, v_a, 16 + e);
            const int   c2 = __shfl_sync(0xffffffffu, c_b, e);
            const float v2 = __shfl_sync(0xffffffffu, v_b, e);
            const int   c3 = __shfl_sync(0xffffffffu, c_b, 16 + e);
            const float v3 = __shfl_sync(0xffffffffu, v_b, 16 + e);
            const float2 h0 = unpack_f16x2(
                *reinterpret_cast<const uint32_t*>(H + (size_t)c0 * HID + 2 * lane));
            const float2 h1 = unpack_f16x2(
                *reinterpret_cast<const uint32_t*>(H + (size_t)c1 * HID + 2 * lane));
            const float2 h2 = unpack_f16x2(
                *reinterpret_cast<const uint32_t*>(H + (size_t)c2 * HID + 2 * lane));
            const float2 h3 = unpack_f16x2(
                *reinterpret_cast<const uint32_t*>(H + (size_t)c3 * HID + 2 * lane));
            ax[0] += v0 * h0.x;  ay[0] += v0 * h0.y;
            ax[1] += v1 * h1.x;  ay[1] += v1 * h1.y;
            ax[2] += v2 * h2.x;  ay[2] += v2 * h2.y;
            ax[3] += v3 * h3.x;  ay[3] += v3 * h3.y;
        }
    } else {
        nrows = min(4, NROWS - row0);
        for (int r = 0; r < nrows; ++r) {
            const int row = row0 + r;
            for (int e = rowptr[row]; e < rowptr[row + 1]; ++e) {
                const int   col = colind[e];
                const float v   = vals[e];
                const float2 h  = unpack_f16x2(
                    *reinterpret_cast<const uint32_t*>(H + (size_t)col * HID + 2 * lane));
                ax[r] += v * h.x;  ay[r] += v * h.y;
            }
        }
    }

    #pragma unroll
    for (int r = 0; r < 4; ++r) {
        Hs[warp][r][2 * lane]     = fmaxf(ax[r], 0.f);
        Hs[warp][r][2 * lane + 1] = fmaxf(ay[r], 0.f);
    }
    __syncwarp();

    float ox[4] = {0.f, 0.f, 0.f, 0.f};
    float oy[4] = {0.f, 0.f, 0.f, 0.f};
    #pragma unroll
    for (int j = 0; j < HID; ++j) {
        const float2 w =
            *reinterpret_cast<const float2*>(W2s + j * OUTD + 2 * lane);
        #pragma unroll
        for (int r = 0; r < 4; ++r) {
            const float a = Hs[warp][r][j];
            ox[r] += a * w.x;  oy[r] += a * w.y;
        }
    }

    #pragma unroll
    for (int r = 0; r < 4; ++r) {
        if (r < nrows)
            *reinterpret_cast<uint32_t*>(O + (size_t)(row0 + r) * OUTD + 2 * lane) =
                pack_f16x2(ox[r], oy[r]);
    }
}

// ---------------------------------------------------------------------------
// Kernel 3: out = A @ O   — unchanged round-14/15 winner
// ---------------------------------------------------------------------------
__global__ void __launch_bounds__(256) spmm2_kernel(
    const __half* __restrict__ O, const float* __restrict__ vals,
    const int* __restrict__ rowptr, const int* __restrict__ colind,
    float* __restrict__ out)
{
    const int tid  = threadIdx.x;
    const int warp = tid >> 5;
    const int lane = tid & 31;
    const int row0 = (blockIdx.x * 8 + warp) * 4;
    if (row0 >= NROWS) return;

    const int s0   = rowptr[row0];
    const int send = rowptr[min(row0 + 4, NROWS)];
    const int nedg = send - s0;

    float ax[4] = {0.f, 0.f, 0.f, 0.f};
    float ay[4] = {0.f, 0.f, 0.f, 0.f};

    if (nedg == 64) {
        const int   c_a = __ldg(colind + s0 + lane);
        const float v_a = __ldg(vals + s0 + lane);
        const int   c_b = __ldg(colind + s0 + 32 + lane);
        const float v_b = __ldg(vals + s0 + 32 + lane);
        #pragma unroll
        for (int e = 0; e < 16; ++e) {
            const int   c0 = __shfl_sync(0xffffffffu, c_a, e);
            const float v0 = __shfl_sync(0xffffffffu, v_a, e);
            const int   c1 = __shfl_sync(0xffffffffu, c_a, 16 + e);
            const float v1 = __shfl_sync(0xffffffffu, v_a, 16 + e);
            const int   c2 = __shfl_sync(0xffffffffu, c_b, e);
            const float v2 = __shfl_sync(0xffffffffu, v_b, e);
            const int   c3 = __shfl_sync(0xffffffffu, c_b, 16 + e);
            const float v3 = __shfl_sync(0xffffffffu, v_b, 16 + e);
            const float2 o0 = unpack_f16x2(
                *reinterpret_cast<const uint32_t*>(O + (size_t)c0 * OUTD + 2 * lane));
            const float2 o1 = unpack_f16x2(
                *reinterpret_cast<const uint32_t*>(O + (size_t)c1 * OUTD + 2 * lane));
            const float2 o2 = unpack_f16x2(
                *reinterpret_cast<const uint32_t*>(O + (size_t)c2 * OUTD + 2 * lane));
            const float2 o3 = unpack_f16x2(
                *reinterpret_cast<const uint32_t*>(O + (size_t)c3 * OUTD + 2 * lane));
            ax[0] += v0 * o0.x;  ay[0] += v0 * o0.y;
            ax[1] += v1 * o1.x;  ay[1] += v1 * o1.y;
            ax[2] += v2 * o2.x;  ay[2] += v2 * o2.y;
            ax[3] += v3 * o3.x;  ay[3] += v3 * o3.y;
        }
        #pragma unroll
        for (int r = 0; r < 4; ++r)
            *reinterpret_cast<float2*>(out + (size_t)(row0 + r) * OUTD + 2 * lane) =
                make_float2(ax[r], ay[r]);
    } else {
        for (int r = 0; r < 4; ++r) {
            const int row = row0 + r;
            if (row >= NROWS) break;
            float bx = 0.f, by = 0.f;
            for (int e = rowptr[row]; e < rowptr[row + 1]; ++e) {
                const int   col = colind[e];
                const float v   = vals[e];
                const float2 o  = unpack_f16x2(
                    *reinterpret_cast<const uint32_t*>(O + (size_t)col * OUTD + 2 * lane));
                bx += v * o.x;  by += v * o.y;
            }
            *reinterpret_cast<float2*>(out + (size_t)row * OUTD + 2 * lane) =
                make_float2(bx, by);
        }
    }
}

// ---------------------------------------------------------------------------
extern "C" void kernel_launch(void* const* d_in, const int* in_sizes, int n_in,
                              void* d_out, int out_size)
{
    const float* X      = (const float*)d_in[0];
    const float* W1     = (const float*)d_in[1];
    const float* W2     = (const float*)d_in[2];
    const float* vals   = (const float*)d_in[3];
    const int*   rowptr = (const int*)d_in[4];
    const int*   colind = (const int*)d_in[5];
    float*       out    = (float*)d_out;

    __half* H; cudaGetSymbolAddress((void**)&H, g_H);
    __half* O; cudaGetSymbolAddress((void**)&O, g_O);

    static bool attr_set = false;
    if (!attr_set) {
        cudaFuncSetAttribute(gemm1_mma_kernel,
                             cudaFuncAttributeMaxDynamicSharedMemorySize, SMEM1);
        attr_set = true;
    }

    gemm1_mma_kernel<<<(NROWS + 255) / 256, 256, SMEM1>>>(X, W1, H);
    spmm_relu_gemm2_kernel<<<(NROWS + 31) / 32, 256>>>(H, W2, vals, rowptr,
                                                       colind, O);
    spmm2_kernel<<<(NROWS + 31) / 32, 256>>>(O, vals, rowptr, colind, out);
}

// round 17
// speedup vs baseline: 1.2563x; 1.0267x over previous
#include <cuda_runtime.h>
#include <cuda_fp16.h>
#include <cstdint>

#define NROWS 100000
#define INDIM 256
#define HID   64
#define OUTD  64

// scratch (device globals: no allocation allowed) — fp16 halves gather bytes
__device__ __align__(16) __half g_H[(size_t)NROWS * HID];
__device__ __align__(16) __half g_O[(size_t)NROWS * OUTD];

// m16n8k16 fp16 MMA, f32 accumulate (baseline PTX, works on .target sm_103)
#define MMA_F16(c0, c1, c2, c3, a0, a1, a2, a3, b0, b1)                       \
    asm volatile(                                                             \
        "mma.sync.aligned.m16n8k16.row.col.f32.f16.f16.f32 "                  \
        "{%0,%1,%2,%3}, {%4,%5,%6,%7}, {%8,%9}, {%0,%1,%2,%3};"               \
        : "+f"(c0), "+f"(c1), "+f"(c2), "+f"(c3)                              \
        : "r"(a0), "r"(a1), "r"(a2), "r"(a3), "r"(b0), "r"(b1))

#define CP_ASYNC16(dst_u32, src_ptr)                                          \
    asm volatile("cp.async.cg.shared.global [%0], [%1], 16;"                  \
                 :: "r"(dst_u32), "l"(src_ptr))
#define CP_COMMIT()  asm volatile("cp.async.commit_group;")
#define CP_WAIT2()   asm volatile("cp.async.wait_group 2;")

__device__ __forceinline__ uint32_t pack_f16x2(float x, float y) {
    const __half2 h = __floats2half2_rn(x, y);
    return *reinterpret_cast<const uint32_t*>(&h);
}
__device__ __forceinline__ float2 unpack_f16x2(uint32_t p) {
    const __half2 h = *reinterpret_cast<const __half2*>(&p);
    return __half22float2(h);
}

#define BSTRIDE 264         // B tile: 256 + 8 fp16 padding, conflict-free
#define BBYTES  (64 * BSTRIDE * 2)           // 33792 (single fp16 W tile)
#define XSTAGEF 2048        // floats per X stage (128 rows x 16 cols)
#define NSTAGE  3
#define SMEM1   (BBYTES + NSTAGE * XSTAGEF * 4)   // 58368 B

// X smem offset (floats) with 16B-chunk XOR swizzle: conflict-free frags
__device__ __forceinline__ int xs_off(int row, int col) {
    return row * 16 + ((((col >> 2) ^ row) & 3) << 2) + (col & 3);
}

// ---------------------------------------------------------------------------
// Kernel 1: H = X @ W1, fp16 MMA, fp32 accum.  M-tile = 128 rows (782 blocks,
// small tail), depth-3 cp.async pipeline, 3 CTAs/SM.
// Warp w: rows w*16..w*16+15, all 64 cols -> 8 MMAs per k-step.
// ---------------------------------------------------------------------------
__global__ void __launch_bounds__(256, 3) gemm1_mma_kernel(
    const float* __restrict__ X, const float* __restrict__ W1,
    __half* __restrict__ H)
{
    extern __shared__ char sraw[];
    __half* Bs = reinterpret_cast<__half*>(sraw);          // [64][BSTRIDE]
    float* Xst = reinterpret_cast<float*>(sraw + BBYTES);
    const uint32_t xbase = (uint32_t)__cvta_generic_to_shared(Xst);

    const int tid  = threadIdx.x;
    const int warp = tid >> 5;
    const int lane = tid & 31;
    const int rbase_blk = blockIdx.x * 128;

    // stage = 128 rows x 16 cols fp32 = 512 16B-chunks; 2 per thread
    auto issue = [&](int ks, int st) {
        const int kb = ks * 16;
        #pragma unroll
        for (int i = 0; i < 2; ++i) {
            const int idx = tid + i * 256;        // 0..511
            const int row = idx >> 2;
            const int ch  = idx & 3;
            const int grow = min(rbase_blk + row, NROWS - 1);
            const float* src = X + (size_t)grow * INDIM + kb + ch * 4;
            const uint32_t dst =
                xbase + ((st * XSTAGEF + row * 16 + (((ch ^ row) & 3) << 2)) << 2);
            CP_ASYNC16(dst, src);
        }
        CP_COMMIT();
    };

    issue(0, 0);
    issue(1, 1);
    issue(2, 2);

    // convert W1 (k-major [256][64]) -> smem n-major fp16
    for (int idx = tid; idx < INDIM * HID; idx += 256) {
        const int k = idx >> 6;
        const int n = idx & 63;
        Bs[n * BSTRIDE + k] = __float2half_rn(W1[idx]);
    }

    const int rq = lane >> 2;         // 0..7
    const int cq = (lane & 3) * 2;    // 0,2,4,6
    const int lrb = warp * 16;        // local row base (16 rows per warp)

    float acc[8][4];
    #pragma unroll
    for (int n = 0; n < 8; ++n)
        #pragma unroll
        for (int i = 0; i < 4; ++i) acc[n][i] = 0.f;

    #pragma unroll 4
    for (int ks = 0; ks < 16; ++ks) {
        CP_WAIT2();          // stage ks arrived (<=2 younger pending)
        __syncthreads();

        const float* Xs = Xst + (ks % NSTAGE) * XSTAGEF;

        uint32_t a[4];
        {
            const int r0 = lrb + rq;
            const int r1 = r0 + 8;
            const float2 f0 = *reinterpret_cast<const float2*>(Xs + xs_off(r0, cq));
            const float2 f1 = *reinterpret_cast<const float2*>(Xs + xs_off(r1, cq));
            const float2 f2 = *reinterpret_cast<const float2*>(Xs + xs_off(r0, cq + 8));
            const float2 f3 = *reinterpret_cast<const float2*>(Xs + xs_off(r1, cq + 8));
            a[0] = pack_f16x2(f0.x, f0.y);
            a[1] = pack_f16x2(f1.x, f1.y);
            a[2] = pack_f16x2(f2.x, f2.y);
            a[3] = pack_f16x2(f3.x, f3.y);
        }

        const int kb = ks * 16;
        #pragma unroll
        for (int n = 0; n < 8; ++n) {
            const int boff = (n * 8 + rq) * BSTRIDE + kb + cq;
            const uint32_t b0 = *reinterpret_cast<const uint32_t*>(Bs + boff);
            const uint32_t b1 = *reinterpret_cast<const uint32_t*>(Bs + boff + 8);
            MMA_F16(acc[n][0], acc[n][1], acc[n][2], acc[n][3],
                    a[0], a[1], a[2], a[3], b0, b1);
        }

        __syncthreads();     // stage ks consumed
        if (ks + 3 < 16) issue(ks + 3, (ks + 3) % NSTAGE);
        else             CP_COMMIT();
    }

    const int r0 = rbase_blk + lrb + rq;
    const int r1 = r0 + 8;
    #pragma unroll
    for (int n = 0; n < 8; ++n) {
        const int col = n * 8 + cq;
        if (r0 < NROWS)
            *reinterpret_cast<uint32_t*>(H + (size_t)r0 * HID + col) =
                pack_f16x2(acc[n][0], acc[n][1]);
        if (r1 < NROWS)
            *reinterpret_cast<uint32_t*>(H + (size_t)r1 * HID + col) =
                pack_f16x2(acc[n][2], acc[n][3]);
    }
}

// ---------------------------------------------------------------------------
// Kernel 2 (fused): O = relu(A @ H) @ W2   — unchanged round-16 winner
// ---------------------------------------------------------------------------
__global__ void __launch_bounds__(256) spmm_relu_gemm2_kernel(
    const __half* __restrict__ H, const float* __restrict__ W2,
    const float* __restrict__ vals, const int* __restrict__ rowptr,
    const int* __restrict__ colind, __half* __restrict__ O)
{
    __shared__ float W2s[HID * OUTD];
    __shared__ float Hs[8][4][HID];

    const int tid = threadIdx.x;
    {
        const float4* src = reinterpret_cast<const float4*>(W2);
        float4* dst = reinterpret_cast<float4*>(W2s);
        #pragma unroll
        for (int i = tid; i < (HID * OUTD) / 4; i += 256) dst[i] = src[i];
    }
    __syncthreads();

    const int warp = tid >> 5;
    const int lane = tid & 31;
    const int row0 = (blockIdx.x * 8 + warp) * 4;
    if (row0 >= NROWS) return;

    const int s0   = rowptr[row0];
    const int send = rowptr[min(row0 + 4, NROWS)];
    const int nedg = send - s0;

    float ax[4] = {0.f, 0.f, 0.f, 0.f};
    float ay[4] = {0.f, 0.f, 0.f, 0.f};
    int nrows = 4;

    if (nedg == 64) {
        const int   c_a = __ldg(colind + s0 + lane);
        const float v_a = __ldg(vals + s0 + lane);
        const int   c_b = __ldg(colind + s0 + 32 + lane);
        const float v_b = __ldg(vals + s0 + 32 + lane);
        #pragma unroll
        for (int e = 0; e < 16; ++e) {
            const int   c0 = __shfl_sync(0xffffffffu, c_a, e);
            const float v0 = __shfl_sync(0xffffffffu, v_a, e);
            const int   c1 = __shfl_sync(0xffffffffu, c_a, 16 + e);
            const float v1 = __shfl_sync(0xffffffffu, v_a, 16 + e);
            const int   c2 = __shfl_sync(0xffffffffu, c_b, e);
            const float v2 = __shfl_sync(0xffffffffu, v_b, e);
            const int   c3 = __shfl_sync(0xffffffffu, c_b, 16 + e);
            const float v3 = __shfl_sync(0xffffffffu, v_b, 16 + e);
            const float2 h0 = unpack_f16x2(
                *reinterpret_cast<const uint32_t*>(H + (size_t)c0 * HID + 2 * lane));
            const float2 h1 = unpack_f16x2(
                *reinterpret_cast<const uint32_t*>(H + (size_t)c1 * HID + 2 * lane));
            const float2 h2 = unpack_f16x2(
                *reinterpret_cast<const uint32_t*>(H + (size_t)c2 * HID + 2 * lane));
            const float2 h3 = unpack_f16x2(
                *reinterpret_cast<const uint32_t*>(H + (size_t)c3 * HID + 2 * lane));
            ax[0] += v0 * h0.x;  ay[0] += v0 * h0.y;
            ax[1] += v1 * h1.x;  ay[1] += v1 * h1.y;
            ax[2] += v2 * h2.x;  ay[2] += v2 * h2.y;
            ax[3] += v3 * h3.x;  ay[3] += v3 * h3.y;
        }
    } else {
        nrows = min(4, NROWS - row0);
        for (int r = 0; r < nrows; ++r) {
            const int row = row0 + r;
            for (int e = rowptr[row]; e < rowptr[row + 1]; ++e) {
                const int   col = colind[e];
                const float v   = vals[e];
                const float2 h  = unpack_f16x2(
                    *reinterpret_cast<const uint32_t*>(H + (size_t)col * HID + 2 * lane));
                ax[r] += v * h.x;  ay[r] += v * h.y;
            }
        }
    }

    #pragma unroll
    for (int r = 0; r < 4; ++r) {
        Hs[warp][r][2 * lane]     = fmaxf(ax[r], 0.f);
        Hs[warp][r][2 * lane + 1] = fmaxf(ay[r], 0.f);
    }
    __syncwarp();

    float ox[4] = {0.f, 0.f, 0.f, 0.f};
    float oy[4] = {0.f, 0.f, 0.f, 0.f};
    #pragma unroll
    for (int j = 0; j < HID; ++j) {
        const float2 w =
            *reinterpret_cast<const float2*>(W2s + j * OUTD + 2 * lane);
        #pragma unroll
        for (int r = 0; r < 4; ++r) {
            const float a = Hs[warp][r][j];
            ox[r] += a * w.x;  oy[r] += a * w.y;
        }
    }

    #pragma unroll
    for (int r = 0; r < 4; ++r) {
        if (r < nrows)
            *reinterpret_cast<uint32_t*>(O + (size_t)(row0 + r) * OUTD + 2 * lane) =
                pack_f16x2(ox[r], oy[r]);
    }
}

// ---------------------------------------------------------------------------
// Kernel 3: out = A @ O   — unchanged round-16 winner
// ---------------------------------------------------------------------------
__global__ void __launch_bounds__(256) spmm2_kernel(
    const __half* __restrict__ O, const float* __restrict__ vals,
    const int* __restrict__ rowptr, const int* __restrict__ colind,
    float* __restrict__ out)
{
    const int tid  = threadIdx.x;
    const int warp = tid >> 5;
    const int lane = tid & 31;
    const int row0 = (blockIdx.x * 8 + warp) * 4;
    if (row0 >= NROWS) return;

    const int s0   = rowptr[row0];
    const int send = rowptr[min(row0 + 4, NROWS)];
    const int nedg = send - s0;

    float ax[4] = {0.f, 0.f, 0.f, 0.f};
    float ay[4] = {0.f, 0.f, 0.f, 0.f};

    if (nedg == 64) {
        const int   c_a = __ldg(colind + s0 + lane);
        const float v_a = __ldg(vals + s0 + lane);
        const int   c_b = __ldg(colind + s0 + 32 + lane);
        const float v_b = __ldg(vals + s0 + 32 + lane);
        #pragma unroll
        for (int e = 0; e < 16; ++e) {
            const int   c0 = __shfl_sync(0xffffffffu, c_a, e);
            const float v0 = __shfl_sync(0xffffffffu, v_a, e);
            const int   c1 = __shfl_sync(0xffffffffu, c_a, 16 + e);
            const float v1 = __shfl_sync(0xffffffffu, v_a, 16 + e);
            const int   c2 = __shfl_sync(0xffffffffu, c_b, e);
            const float v2 = __shfl_sync(0xffffffffu, v_b, e);
            const int   c3 = __shfl_sync(0xffffffffu, c_b, 16 + e);
            const float v3 = __shfl_sync(0xffffffffu, v_b, 16 + e);
            const float2 o0 = unpack_f16x2(
                *reinterpret_cast<const uint32_t*>(O + (size_t)c0 * OUTD + 2 * lane));
            const float2 o1 = unpack_f16x2(
                *reinterpret_cast<const uint32_t*>(O + (size_t)c1 * OUTD + 2 * lane));
            const float2 o2 = unpack_f16x2(
                *reinterpret_cast<const uint32_t*>(O + (size_t)c2 * OUTD + 2 * lane));
            const float2 o3 = unpack_f16x2(
                *reinterpret_cast<const uint32_t*>(O + (size_t)c3 * OUTD + 2 * lane));
            ax[0] += v0 * o0.x;  ay[0] += v0 * o0.y;
            ax[1] += v1 * o1.x;  ay[1] += v1 * o1.y;
            ax[2] += v2 * o2.x;  ay[2] += v2 * o2.y;
            ax[3] += v3 * o3.x;  ay[3] += v3 * o3.y;
        }
        #pragma unroll
        for (int r = 0; r < 4; ++r)
            *reinterpret_cast<float2*>(out + (size_t)(row0 + r) * OUTD + 2 * lane) =
                make_float2(ax[r], ay[r]);
    } else {
        for (int r = 0; r < 4; ++r) {
            const int row = row0 + r;
            if (row >= NROWS) break;
            float bx = 0.f, by = 0.f;
            for (int e = rowptr[row]; e < rowptr[row + 1]; ++e) {
                const int   col = colind[e];
                const float v   = vals[e];
                const float2 o  = unpack_f16x2(
                    *reinterpret_cast<const uint32_t*>(O + (size_t)col * OUTD + 2 * lane));
                bx += v * o.x;  by += v * o.y;
            }
            *reinterpret_cast<float2*>(out + (size_t)row * OUTD + 2 * lane) =
                make_float2(bx, by);
        }
    }
}

// ---------------------------------------------------------------------------
extern "C" void kernel_launch(void* const* d_in, const int* in_sizes, int n_in,
                              void* d_out, int out_size)
{
    const float* X      = (const float*)d_in[0];
    const float* W1     = (const float*)d_in[1];
    const float* W2     = (const float*)d_in[2];
    const float* vals   = (const float*)d_in[3];
    const int*   rowptr = (const int*)d_in[4];
    const int*   colind = (const int*)d_in[5];
    float*       out    = (float*)d_out;

    __half* H; cudaGetSymbolAddress((void**)&H, g_H);
    __half* O; cudaGetSymbolAddress((void**)&O, g_O);

    static bool attr_set = false;
    if (!attr_set) {
        cudaFuncSetAttribute(gemm1_mma_kernel,
                             cudaFuncAttributeMaxDynamicSharedMemorySize, SMEM1);
        attr_set = true;
    }

    gemm1_mma_kernel<<<(NROWS + 127) / 128, 256, SMEM1>>>(X, W1, H);
    spmm_relu_gemm2_kernel<<<(NROWS + 31) / 32, 256>>>(H, W2, vals, rowptr,
                                                       colind, O);
    spmm2_kernel<<<(NROWS + 31) / 32, 256>>>(O, vals, rowptr, colind, out);
}